// round 1
// baseline (speedup 1.0000x reference)
#include <cuda_runtime.h>
#include <math.h>

// Problem constants (fixed shapes from the dataset)
#define BB   128
#define NN   128
#define MM   64
#define NG   20
#define NA   10     // angular components for lmax=2
#define FPS  600    // NG * (LMAX+1) * NMBODY = 20*3*10

#define SQRTPI_F 1.7724538509055160273f

// angw = multinomial weights per angular component
__constant__ float c_angw[NA] = {1.f,1.f,1.f,1.f,1.f,2.f,1.f,2.f,2.f,1.f};
// combos (i,j) for the 6 pair terms, order matches reference COMBOS
__constant__ int c_ci[6] = {0,0,0,1,1,2};
__constant__ int c_cj[6] = {1,2,3,2,3,3};

__device__ __forceinline__ float pick4(const float4 t, int i) {
    return (i == 0) ? t.x : ((i == 1) ? t.y : ((i == 2) ? t.z : t.w));
}

__global__ __launch_bounds__(256, 8)
void fp_kernel(const float* __restrict__ coords,
               const int*   __restrict__ charges,
               const int*   __restrict__ counts,
               const int*   __restrict__ neigh,
               float*       __restrict__ out)
{
    const int atom = blockIdx.x;          // b*NN + n
    const int b = atom >> 7;              // NN = 128
    const int n = atom & 127;
    const int tid = threadIdx.x;

    float* outp = out + (size_t)atom * FPS;

    // masked atoms: reference multiplies fp by 0 -> write zeros
    if (n >= counts[b]) {
        for (int o = tid; o < FPS; o += 256) outp[o] = 0.0f;
        return;
    }

    __shared__ float s_rad[MM * NG];      // 1280
    __shared__ float s_ang[MM * NA];      // 640
    __shared__ float s_nbx[MM], s_nby[MM], s_nbz[MM];
    __shared__ float s_mu[MM], s_i2s[MM], s_c0[MM], s_invd[MM];
    __shared__ int   s_spec[MM];
    __shared__ float s_logoff[NG], s_invoff[NG];
    __shared__ float4 s_t[NA * NG];       // [a][g] -> (t0,t1,t2,t3)

    // ---- offset tables (threads 224..243) ----
    if (tid >= 224 && tid < 224 + NG) {
        int g = tid - 224;
        float off = 0.3f * (float)(g + 1);   // linspace(0,6,21)[1:]
        s_logoff[g] = logf(off);
        s_invoff[g] = 1.0f / off;
    }

    // ---- phase A: per-neighbour scalars (threads 0..63) ----
    if (tid < MM) {
        const int m = tid;
        const int nbraw = neigh[(size_t)atom * MM + m];
        const bool valid = nbraw >= 0;
        const int nb = valid ? nbraw : 0;

        const float ax = coords[(size_t)atom * 3 + 0];
        const float ay = coords[(size_t)atom * 3 + 1];
        const float az = coords[(size_t)atom * 3 + 2];
        const size_t nbase = ((size_t)b * NN + nb) * 3;
        float dx = ax - coords[nbase + 0];
        float dy = ay - coords[nbase + 1];
        float dz = az - coords[nbase + 2];
        if (!valid) { dx = 1.0f; dy = 1.0f; dz = 1.0f; }

        const float d2 = dx*dx + dy*dy + dz*dz;
        const float d  = sqrtf(d2);
        const float sig2 = log1pf(2.0f / d2);         // W = 2
        const float mu   = logf(d) - 0.5f * sig2;
        const float dsw  = (d - 1.0f) * 0.2f;         // (d-RSWITCH)/(HIGH-RSWITCH)
        const float dsw2 = dsw * dsw;
        const float dsw3 = dsw2 * dsw;
        const float cut  = 1.0f - dsw3 * (10.0f - 15.0f*dsw + 6.0f*dsw2);

        const int z = charges[(size_t)b * NN + nb];
        const int sp = (z == 1) ? 0 : ((z == 6) ? 1 : ((z == 7) ? 2 : 3));

        s_nbx[m] = dx; s_nby[m] = dy; s_nbz[m] = dz;
        s_mu[m]   = mu;
        s_i2s[m]  = 0.5f / sig2;
        s_c0[m]   = valid ? (cut * rsqrtf(sig2) * (1.0f / SQRTPI_F)) : 0.0f;
        s_invd[m] = valid ? (1.0f / d) : 0.0f;
        s_spec[m] = sp;
    }
    __syncthreads();

    // ---- phase B: radial [m][g] and angular [m][a] tables ----
    for (int idx = tid; idx < MM * NG; idx += 256) {
        const int m = idx / NG;
        const int g = idx - m * NG;
        const float c = s_logoff[g] - s_mu[m];
        s_rad[idx] = s_c0[m] * s_invoff[g] * expf(-c * c * s_i2s[m]);
    }
    for (int idx = tid; idx < MM * NA; idx += 256) {
        const int m = idx / NA;
        const int a = idx - m * NA;
        const float x = s_nbx[m], y = s_nby[m], zc = s_nbz[m];
        const float id  = s_invd[m];
        const float i2  = id * id;
        const float i3  = i2 * id;
        const float i4  = i2 * i2;
        float v;
        switch (a) {
            case 0: v = i2;           break;
            case 1: v = i3 * x;       break;
            case 2: v = i3 * y;       break;
            case 3: v = i3 * zc;      break;
            case 4: v = i4 * x * x;   break;
            case 5: v = i4 * x * y;   break;
            case 6: v = i4 * y * y;   break;
            case 7: v = i4 * x * zc;  break;
            case 8: v = i4 * y * zc;  break;
            default: v = i4 * zc * zc; break;
        }
        s_ang[idx] = v;
    }
    __syncthreads();

    // ---- accumulate: thread (a,g) owns 4 per-species accumulators ----
    if (tid < NA * NG) {
        const int a = tid / NG;
        const int g = tid - a * NG;
        float t0 = 0.f, t1 = 0.f, t2 = 0.f, t3 = 0.f;
        const float* angp = s_ang + a;
        const float* radp = s_rad + g;
        #pragma unroll 8
        for (int m = 0; m < MM; m++) {
            const float prod = angp[m * NA] * radp[m * NG];
            const int sp = s_spec[m];           // uniform across block -> no divergence
            if      (sp == 0) t0 += prod;
            else if (sp == 1) t1 += prod;
            else if (sp == 2) t2 += prod;
            else              t3 += prod;
        }
        s_t[tid] = make_float4(t0, t1, t2, t3);
    }
    __syncthreads();

    // ---- epilogue: 600 outputs.  fp[l][mb][g]; LWEIGHTS = 1 ----
    // species s: sum_a angw * t_s^2 ;  combo (i,j): sum_a 2*angw*t_i*t_j
    for (int o = tid; o < FPS; o += 256) {
        const int g    = o % NG;
        const int rest = o / NG;
        const int mb   = rest % 10;
        const int l    = rest / 10;
        const int a0 = (l == 0) ? 0 : ((l == 1) ? 1 : 4);
        const int a1 = (l == 0) ? 1 : ((l == 1) ? 4 : 10);
        float val = 0.0f;
        if (mb < 4) {
            for (int a = a0; a < a1; a++) {
                const float4 t = s_t[a * NG + g];
                const float ts = pick4(t, mb);
                val += c_angw[a] * ts * ts;
            }
        } else {
            const int cidx = mb - 4;
            const int i = c_ci[cidx], j = c_cj[cidx];
            for (int a = a0; a < a1; a++) {
                const float4 t = s_t[a * NG + g];
                val += 2.0f * c_angw[a] * pick4(t, i) * pick4(t, j);
            }
        }
        outp[o] = val;
    }
}

extern "C" void kernel_launch(void* const* d_in, const int* in_sizes, int n_in,
                              void* d_out, int out_size) {
    const float* coords  = (const float*)d_in[0];
    const int*   charges = (const int*)d_in[1];
    const int*   counts  = (const int*)d_in[2];
    const int*   neigh   = (const int*)d_in[3];
    float* out = (float*)d_out;
    (void)n_in; (void)out_size;

    const int B = in_sizes[2];            // natom_counts has B elements
    const int N = in_sizes[1] / B;        // nuclear_charges is B*N
    dim3 grid(B * N);
    fp_kernel<<<grid, 256>>>(coords, charges, counts, neigh, out);
}

// round 2
// speedup vs baseline: 1.2112x; 1.2112x over previous
#include <cuda_runtime.h>
#include <math.h>

// Problem constants (fixed shapes from the dataset)
#define NN   128
#define MM   64
#define NG   20
#define NA   10     // angular components for lmax=2
#define FPS  600    // NG * (LMAX+1) * NMBODY
#define MMP  65     // padded m-stride (65 mod 32 == 1 -> conflict-free)

#define SQRTPI_F 1.7724538509055160273f

__constant__ float c_angw[NA] = {1.f,1.f,1.f,1.f,1.f,2.f,1.f,2.f,2.f,1.f};
__constant__ int c_ci[6] = {0,0,0,1,1,2};
__constant__ int c_cj[6] = {1,2,3,2,3,3};

__device__ __forceinline__ float pick4(const float4 t, int i) {
    return (i == 0) ? t.x : ((i == 1) ? t.y : ((i == 2) ? t.z : t.w));
}

__global__ __launch_bounds__(256, 8)
void fp_kernel(const float* __restrict__ coords,
               const int*   __restrict__ charges,
               const int*   __restrict__ counts,
               const int*   __restrict__ neigh,
               float*       __restrict__ out)
{
    const int atom = blockIdx.x;          // b*NN + n
    const int b = atom >> 7;              // NN = 128
    const int n = atom & 127;
    const int tid = threadIdx.x;

    float* outp = out + (size_t)atom * FPS;

    if (n >= counts[b]) {
        for (int o = tid; o < FPS; o += 256) outp[o] = 0.0f;
        return;
    }

    __shared__ float s_rad[NG * MMP];     // [g][m] transposed, padded
    __shared__ float s_ang[NA * MMP];     // [a][m] transposed, padded
    __shared__ float s_nbx[MM], s_nby[MM], s_nbz[MM];
    __shared__ float s_mu[MM], s_i2s[MM], s_c0[MM], s_invd[MM];
    __shared__ float s_logoff[NG], s_invoff[NG];
    __shared__ int   s_wcnt[2][4];        // per-warp species counts (warps 0,1 of phase A)
    __shared__ int   s_seg[5];            // species segment boundaries
    __shared__ float4 s_t[NA * NG];       // [a][g] -> per-species accumulators

    // ---- offset tables ----
    if (tid >= 224 && tid < 224 + NG) {
        int g = tid - 224;
        float off = 0.3f * (float)(g + 1);
        s_logoff[g] = logf(off);
        s_invoff[g] = 1.0f / off;
    }

    // ---- phase A: per-neighbour scalars, sorted by species ----
    int my_sp = 0, b0, b1, b2, b3;
    float r_dx, r_dy, r_dz, r_mu, r_i2s, r_c0, r_invd;
    if (tid < MM) {
        const int m = tid;
        const int w = tid >> 5;
        const int lane = tid & 31;
        const int nbraw = neigh[(size_t)atom * MM + m];
        const bool valid = nbraw >= 0;
        const int nb = valid ? nbraw : 0;

        const float ax = coords[(size_t)atom * 3 + 0];
        const float ay = coords[(size_t)atom * 3 + 1];
        const float az = coords[(size_t)atom * 3 + 2];
        const size_t nbase = ((size_t)b * NN + nb) * 3;
        float dx = ax - coords[nbase + 0];
        float dy = ay - coords[nbase + 1];
        float dz = az - coords[nbase + 2];
        if (!valid) { dx = 1.0f; dy = 1.0f; dz = 1.0f; }

        const float d2 = dx*dx + dy*dy + dz*dz;
        const float d  = sqrtf(d2);
        const float sig2 = log1pf(2.0f / d2);
        const float mu   = logf(d) - 0.5f * sig2;
        const float dsw  = (d - 1.0f) * 0.2f;
        const float dsw2 = dsw * dsw;
        const float dsw3 = dsw2 * dsw;
        const float cut  = 1.0f - dsw3 * (10.0f - 15.0f*dsw + 6.0f*dsw2);

        const int z = charges[(size_t)b * NN + nb];
        my_sp = (z == 1) ? 0 : ((z == 6) ? 1 : ((z == 7) ? 2 : 3));

        r_dx = dx; r_dy = dy; r_dz = dz;
        r_mu = mu;
        r_i2s = 0.5f / sig2;
        r_c0  = valid ? (cut * rsqrtf(sig2) * (1.0f / SQRTPI_F)) : 0.0f;
        r_invd = valid ? (1.0f / d) : 0.0f;

        // deterministic stable counting sort: ballots per species
        b0 = __ballot_sync(0xffffffffu, my_sp == 0);
        b1 = __ballot_sync(0xffffffffu, my_sp == 1);
        b2 = __ballot_sync(0xffffffffu, my_sp == 2);
        b3 = __ballot_sync(0xffffffffu, my_sp == 3);
        if (lane == 0) {
            s_wcnt[w][0] = __popc(b0);
            s_wcnt[w][1] = __popc(b1);
            s_wcnt[w][2] = __popc(b2);
            s_wcnt[w][3] = __popc(b3);
        }
    }
    __syncthreads();

    if (tid == 0) {
        int c0t = s_wcnt[0][0] + s_wcnt[1][0];
        int c1t = s_wcnt[0][1] + s_wcnt[1][1];
        int c2t = s_wcnt[0][2] + s_wcnt[1][2];
        s_seg[0] = 0;
        s_seg[1] = c0t;
        s_seg[2] = c0t + c1t;
        s_seg[3] = c0t + c1t + c2t;
        s_seg[4] = MM;
    }
    __syncthreads();

    if (tid < MM) {
        const int w = tid >> 5;
        const int lane = tid & 31;
        const unsigned below = (lane == 31) ? 0xffffffffu >> 1 : ((1u << lane) - 1u);
        // rank within species across both warps (stable by m)
        int myb = (my_sp == 0) ? b0 : ((my_sp == 1) ? b1 : ((my_sp == 2) ? b2 : b3));
        int rank = __popc((unsigned)myb & ((1u << lane) - 1u));
        if (w == 1) rank += s_wcnt[0][my_sp];
        const int pos = s_seg[my_sp] + rank;
        s_nbx[pos] = r_dx; s_nby[pos] = r_dy; s_nbz[pos] = r_dz;
        s_mu[pos]  = r_mu; s_i2s[pos] = r_i2s;
        s_c0[pos]  = r_c0; s_invd[pos] = r_invd;
        (void)below;
    }
    __syncthreads();

    // ---- phase B: radial [g][m] and angular [a][m] tables (transposed) ----
    for (int idx = tid; idx < MM * NG; idx += 256) {
        const int m = idx / NG;
        const int g = idx - m * NG;
        const float c = s_logoff[g] - s_mu[m];
        s_rad[g * MMP + m] = s_c0[m] * s_invoff[g] * __expf(-c * c * s_i2s[m]);
    }
    for (int idx = tid; idx < MM * NA; idx += 256) {
        const int m = idx / NA;
        const int a = idx - m * NA;
        const float x = s_nbx[m], y = s_nby[m], zc = s_nbz[m];
        const float id  = s_invd[m];
        const float i2  = id * id;
        const float i3  = i2 * id;
        const float i4  = i2 * i2;
        float v;
        switch (a) {
            case 0: v = i2;           break;
            case 1: v = i3 * x;       break;
            case 2: v = i3 * y;       break;
            case 3: v = i3 * zc;      break;
            case 4: v = i4 * x * x;   break;
            case 5: v = i4 * x * y;   break;
            case 6: v = i4 * y * y;   break;
            case 7: v = i4 * x * zc;  break;
            case 8: v = i4 * y * zc;  break;
            default: v = i4 * zc * zc; break;
        }
        s_ang[a * MMP + m] = v;
    }
    __syncthreads();

    // ---- accumulate: thread (a,g); 4 clean per-species segments, FFMA-only ----
    if (tid < NA * NG) {
        const int a = tid / NG;
        const int g = tid - a * NG;
        const float* __restrict__ angp = s_ang + a * MMP;
        const float* __restrict__ radp = s_rad + g * MMP;
        const int e0 = s_seg[1], e1 = s_seg[2], e2 = s_seg[3];

        float t0 = 0.f, t1 = 0.f, t2 = 0.f, t3 = 0.f;
        int m = 0;
        #pragma unroll 4
        for (; m < e0; ++m) t0 = fmaf(angp[m], radp[m], t0);
        #pragma unroll 4
        for (; m < e1; ++m) t1 = fmaf(angp[m], radp[m], t1);
        #pragma unroll 4
        for (; m < e2; ++m) t2 = fmaf(angp[m], radp[m], t2);
        #pragma unroll 4
        for (; m < MM; ++m) t3 = fmaf(angp[m], radp[m], t3);

        s_t[tid] = make_float4(t0, t1, t2, t3);
    }
    __syncthreads();

    // ---- epilogue: 600 outputs ----
    for (int o = tid; o < FPS; o += 256) {
        const int g    = o % NG;
        const int rest = o / NG;
        const int mb   = rest % 10;
        const int l    = rest / 10;
        const int a0 = (l == 0) ? 0 : ((l == 1) ? 1 : 4);
        const int a1 = (l == 0) ? 1 : ((l == 1) ? 4 : 10);
        float val = 0.0f;
        if (mb < 4) {
            for (int a = a0; a < a1; a++) {
                const float4 t = s_t[a * NG + g];
                const float ts = pick4(t, mb);
                val = fmaf(c_angw[a] * ts, ts, val);
            }
        } else {
            const int cidx = mb - 4;
            const int i = c_ci[cidx], j = c_cj[cidx];
            for (int a = a0; a < a1; a++) {
                const float4 t = s_t[a * NG + g];
                val = fmaf(2.0f * c_angw[a] * pick4(t, i), pick4(t, j), val);
            }
        }
        outp[o] = val;
    }
}

extern "C" void kernel_launch(void* const* d_in, const int* in_sizes, int n_in,
                              void* d_out, int out_size) {
    const float* coords  = (const float*)d_in[0];
    const int*   charges = (const int*)d_in[1];
    const int*   counts  = (const int*)d_in[2];
    const int*   neigh   = (const int*)d_in[3];
    float* out = (float*)d_out;
    (void)n_in; (void)out_size;

    const int B = in_sizes[2];
    const int N = in_sizes[1] / B;
    dim3 grid(B * N);
    fp_kernel<<<grid, 256>>>(coords, charges, counts, neigh, out);
}

// round 3
// speedup vs baseline: 1.7042x; 1.4070x over previous
#include <cuda_runtime.h>
#include <math.h>

#define NN   128
#define MM   64
#define MM2  76     // padded neighbour capacity (segments 4-aligned), 76 floats = 19 float4
#define MMP  76     // row stride in floats (16B multiple)
#define NG   20
#define NA   10
#define FPS  600

#define SQRTPI_F 1.7724538509055160273f
#define HLOG2E   0.72134752044448170368f   // 0.5 * log2(e)

__constant__ float c_angw[NA] = {1.f,1.f,1.f,1.f,1.f,2.f,1.f,2.f,2.f,1.f};
__constant__ int c_ci[6] = {0,0,0,1,1,2};
__constant__ int c_cj[6] = {1,2,3,2,3,3};

// log(0.3*(g+1)) and 1/(0.3*(g+1)), g=0..19
__constant__ float c_logoff[NG] = {
    -1.2039728043f, -0.5108256238f, -0.1053605157f,  0.1823215568f,
     0.4054651081f,  0.5877866649f,  0.7419373447f,  0.8754687374f,
     0.9932517730f,  1.0986122887f,  1.1939224685f,  1.2809338455f,
     1.3609765531f,  1.4350845253f,  1.5040773968f,  1.5686159179f,
     1.6292405397f,  1.6863989543f,  1.7404661748f,  1.7917594692f };
__constant__ float c_invoff[NG] = {
    3.3333333333f, 1.6666666667f, 1.1111111111f, 0.8333333333f,
    0.6666666667f, 0.5555555556f, 0.4761904762f, 0.4166666667f,
    0.3703703704f, 0.3333333333f, 0.3030303030f, 0.2777777778f,
    0.2564102564f, 0.2380952381f, 0.2222222222f, 0.2083333333f,
    0.1960784314f, 0.1851851852f, 0.1754385965f, 0.1666666667f };

__device__ __forceinline__ float ex2f(float x) {
    float y;
    asm("ex2.approx.ftz.f32 %0, %1;" : "=f"(y) : "f"(x));
    return y;
}

__device__ __forceinline__ float pick4(const float4 t, int i) {
    return (i == 0) ? t.x : ((i == 1) ? t.y : ((i == 2) ? t.z : t.w));
}

__global__ __launch_bounds__(256, 6)
void fp_kernel(const float* __restrict__ coords,
               const int*   __restrict__ charges,
               const int*   __restrict__ counts,
               const int*   __restrict__ neigh,
               float*       __restrict__ out)
{
    const int atom = blockIdx.x;
    const int b = atom >> 7;              // NN = 128
    const int n = atom & 127;
    const int tid = threadIdx.x;

    float* outp = out + (size_t)atom * FPS;

    if (n >= counts[b]) {
        float4* o4 = (float4*)outp;       // 600 floats = 150 float4, base 16B aligned
        for (int o = tid; o < FPS / 4; o += 256) o4[o] = make_float4(0.f,0.f,0.f,0.f);
        return;
    }

    __shared__ __align__(16) float s_rad[NG * MMP];   // [g][m]
    __shared__ __align__(16) float s_ang[NA * MMP];   // [a][m]
    __shared__ float s_nbx[MM2], s_nby[MM2], s_nbz[MM2];
    __shared__ float s_mu[MM2], s_ni2s[MM2], s_k[MM2], s_invd[MM2];
    __shared__ int   s_wcnt[2][4];
    __shared__ int   s_seg4[5];           // 4-aligned segment starts
    __shared__ float4 s_t[NA * NG];

    // ---- defaults for padded slots (rad -> 0, ang -> 0) ----
    if (tid < MM2) {
        s_mu[tid] = 0.f; s_ni2s[tid] = 0.f; s_k[tid] = 0.f; s_invd[tid] = 0.f;
        s_nbx[tid] = 0.f; s_nby[tid] = 0.f; s_nbz[tid] = 0.f;
    }

    // ---- phase A: per-neighbour scalars + species ballots ----
    int my_sp = 0;
    unsigned bm0 = 0, bm1 = 0, bm2 = 0, bm3 = 0;
    float r_dx = 0.f, r_dy = 0.f, r_dz = 0.f, r_mu = 0.f, r_ni2s = 0.f, r_k = 0.f, r_invd = 0.f;
    if (tid < MM) {
        const int w = tid >> 5;
        const int nbraw = neigh[(size_t)atom * MM + tid];
        const bool valid = nbraw >= 0;
        const int nb = valid ? nbraw : 0;

        const float ax = coords[(size_t)atom * 3 + 0];
        const float ay = coords[(size_t)atom * 3 + 1];
        const float az = coords[(size_t)atom * 3 + 2];
        const size_t nbase = ((size_t)b * NN + nb) * 3;
        float dx = ax - coords[nbase + 0];
        float dy = ay - coords[nbase + 1];
        float dz = az - coords[nbase + 2];
        if (!valid) { dx = 1.0f; dy = 1.0f; dz = 1.0f; }

        const float d2 = dx*dx + dy*dy + dz*dz;
        const float d  = sqrtf(d2);
        const float sig2 = log1pf(2.0f / d2);
        const float mu   = logf(d) - 0.5f * sig2;
        const float dsw  = (d - 1.0f) * 0.2f;
        const float dsw2 = dsw * dsw;
        const float dsw3 = dsw2 * dsw;
        const float cut  = 1.0f - dsw3 * (10.0f - 15.0f*dsw + 6.0f*dsw2);

        const int z = charges[(size_t)b * NN + nb];
        my_sp = (z == 1) ? 0 : ((z == 6) ? 1 : ((z == 7) ? 2 : 3));

        r_dx = dx; r_dy = dy; r_dz = dz;
        r_mu = mu;
        r_ni2s = -HLOG2E / sig2;                                  // exp pre-scaled for ex2
        r_k    = valid ? (cut * rsqrtf(sig2) * (1.0f / SQRTPI_F)) : 0.0f;
        r_invd = valid ? (1.0f / d) : 0.0f;

        bm0 = __ballot_sync(0xffffffffu, my_sp == 0);
        bm1 = __ballot_sync(0xffffffffu, my_sp == 1);
        bm2 = __ballot_sync(0xffffffffu, my_sp == 2);
        bm3 = __ballot_sync(0xffffffffu, my_sp == 3);
        if ((tid & 31) == 0) {
            s_wcnt[w][0] = __popc(bm0);
            s_wcnt[w][1] = __popc(bm1);
            s_wcnt[w][2] = __popc(bm2);
            s_wcnt[w][3] = __popc(bm3);
        }
    }
    __syncthreads();

    if (tid == 0) {
        const int c0 = s_wcnt[0][0] + s_wcnt[1][0];
        const int c1 = s_wcnt[0][1] + s_wcnt[1][1];
        const int c2 = s_wcnt[0][2] + s_wcnt[1][2];
        const int c3 = s_wcnt[0][3] + s_wcnt[1][3];
        int s0 = 0;
        int s1 = (s0 + c0 + 3) & ~3;
        int s2 = (s1 + c1 + 3) & ~3;
        int s3 = (s2 + c2 + 3) & ~3;
        int s4 = (s3 + c3 + 3) & ~3;
        s_seg4[0] = s0; s_seg4[1] = s1; s_seg4[2] = s2; s_seg4[3] = s3; s_seg4[4] = s4;
    }
    __syncthreads();

    // ---- scatter to species-sorted, 4-aligned positions ----
    if (tid < MM) {
        const int w = tid >> 5;
        const int lane = tid & 31;
        const unsigned myb = (my_sp == 0) ? bm0 : ((my_sp == 1) ? bm1 : ((my_sp == 2) ? bm2 : bm3));
        int rank = __popc(myb & ((1u << lane) - 1u));
        if (w == 1) rank += s_wcnt[0][my_sp];
        const int pos = s_seg4[my_sp] + rank;
        s_nbx[pos] = r_dx; s_nby[pos] = r_dy; s_nbz[pos] = r_dz;
        s_mu[pos]  = r_mu; s_ni2s[pos] = r_ni2s;
        s_k[pos]   = r_k;  s_invd[pos] = r_invd;
    }
    __syncthreads();

    // ---- phase B ----
    // radial: threads [0,152) -> 2 threads per m (76 rows), 10 g's each
    if (tid < 2 * MM2) {
        const int m    = tid >> 1;
        const int half = tid & 1;
        const float mu   = s_mu[m];
        const float ni2s = s_ni2s[m];
        const float k    = s_k[m];
        const int g0 = half * 10;
        #pragma unroll
        for (int gg = 0; gg < 10; gg++) {
            const int g = g0 + gg;
            const float c = c_logoff[g] - mu;
            const float e = ex2f(c * c * ni2s);
            s_rad[g * MMP + m] = k * c_invoff[g] * e;
        }
    }
    // angular: threads [152, 152+76) -> one thread per m, 10 a's each
    else if (tid < 2 * MM2 + MM2) {
        const int m = tid - 2 * MM2;
        const float x = s_nbx[m], y = s_nby[m], zc = s_nbz[m];
        const float id = s_invd[m];
        const float i2 = id * id;
        const float i3 = i2 * id;
        const float i4 = i2 * i2;
        s_ang[0 * MMP + m] = i2;
        s_ang[1 * MMP + m] = i3 * x;
        s_ang[2 * MMP + m] = i3 * y;
        s_ang[3 * MMP + m] = i3 * zc;
        s_ang[4 * MMP + m] = i4 * x * x;
        s_ang[5 * MMP + m] = i4 * x * y;
        s_ang[6 * MMP + m] = i4 * y * y;
        s_ang[7 * MMP + m] = i4 * x * zc;
        s_ang[8 * MMP + m] = i4 * y * zc;
        s_ang[9 * MMP + m] = i4 * zc * zc;
    }
    __syncthreads();

    // ---- main loop: thread (a,g); 4 segments in float4 chunks, FFMA-only ----
    if (tid < NA * NG) {
        const int a = tid / NG;
        const int g = tid - a * NG;
        const float4* __restrict__ angp = (const float4*)(s_ang + a * MMP);
        const float4* __restrict__ radp = (const float4*)(s_rad + g * MMP);
        const int e0 = s_seg4[1] >> 2;
        const int e1 = s_seg4[2] >> 2;
        const int e2 = s_seg4[3] >> 2;
        const int e3 = s_seg4[4] >> 2;

        float t0 = 0.f, t1 = 0.f, t2 = 0.f, t3 = 0.f;
        int c = 0;
        #pragma unroll 2
        for (; c < e0; ++c) {
            const float4 av = angp[c], rv = radp[c];
            t0 = fmaf(av.x, rv.x, t0); t0 = fmaf(av.y, rv.y, t0);
            t0 = fmaf(av.z, rv.z, t0); t0 = fmaf(av.w, rv.w, t0);
        }
        #pragma unroll 2
        for (; c < e1; ++c) {
            const float4 av = angp[c], rv = radp[c];
            t1 = fmaf(av.x, rv.x, t1); t1 = fmaf(av.y, rv.y, t1);
            t1 = fmaf(av.z, rv.z, t1); t1 = fmaf(av.w, rv.w, t1);
        }
        #pragma unroll 2
        for (; c < e2; ++c) {
            const float4 av = angp[c], rv = radp[c];
            t2 = fmaf(av.x, rv.x, t2); t2 = fmaf(av.y, rv.y, t2);
            t2 = fmaf(av.z, rv.z, t2); t2 = fmaf(av.w, rv.w, t2);
        }
        #pragma unroll 2
        for (; c < e3; ++c) {
            const float4 av = angp[c], rv = radp[c];
            t3 = fmaf(av.x, rv.x, t3); t3 = fmaf(av.y, rv.y, t3);
            t3 = fmaf(av.z, rv.z, t3); t3 = fmaf(av.w, rv.w, t3);
        }
        s_t[tid] = make_float4(t0, t1, t2, t3);
    }
    __syncthreads();

    // ---- epilogue: 600 outputs ----
    for (int o = tid; o < FPS; o += 256) {
        const int g    = o % NG;
        const int rest = o / NG;
        const int mb   = rest % 10;
        const int l    = rest / 10;
        const int a0 = (l == 0) ? 0 : ((l == 1) ? 1 : 4);
        const int a1 = (l == 0) ? 1 : ((l == 1) ? 4 : 10);
        float val = 0.0f;
        if (mb < 4) {
            for (int a = a0; a < a1; a++) {
                const float4 t = s_t[a * NG + g];
                const float ts = pick4(t, mb);
                val = fmaf(c_angw[a] * ts, ts, val);
            }
        } else {
            const int cidx = mb - 4;
            const int i = c_ci[cidx], j = c_cj[cidx];
            for (int a = a0; a < a1; a++) {
                const float4 t = s_t[a * NG + g];
                val = fmaf(2.0f * c_angw[a] * pick4(t, i), pick4(t, j), val);
            }
        }
        outp[o] = val;
    }
}

extern "C" void kernel_launch(void* const* d_in, const int* in_sizes, int n_in,
                              void* d_out, int out_size) {
    const float* coords  = (const float*)d_in[0];
    const int*   charges = (const int*)d_in[1];
    const int*   counts  = (const int*)d_in[2];
    const int*   neigh   = (const int*)d_in[3];
    float* out = (float*)d_out;
    (void)n_in; (void)out_size;

    const int B = in_sizes[2];
    const int N = in_sizes[1] / B;
    dim3 grid(B * N);
    fp_kernel<<<grid, 256>>>(coords, charges, counts, neigh, out);
}